// round 16
// baseline (speedup 1.0000x reference)
#include <cuda_runtime.h>
#include <cuda_fp16.h>
#include <math.h>

// ---------------- problem constants ----------------
#define B   4
#define N0  8192   // finest
#define N1  2048
#define N2  512    // coarsest
#define D0  128    // x0 channels
#define D1C 256    // x1 channels
#define D2C 512    // x2 channels
#define DI  768    // intermediate channels (D1C + D2C)
#define DT  896    // output channels (D0 + DI)

// ---------------- scratch (device globals; no allocation allowed) ----------------
__device__ __align__(16) __half g_x2t[B * N2 * D2C];   // x2 transposed, fp16 [B,S,D]
__device__ __align__(16) __half g_inter[B * N1 * DI];  // stage-1 result, fp16 point-major
__device__ int    g_idx1[B * N1 * 3];
__device__ float  g_w1[B * N1 * 3];
__device__ int    g_idx2[B * N0 * 3];
__device__ float  g_w2[B * N0 * 3];

// ---------------- transpose [B,R,C] fp32 -> fp16 dst (strided) ----------------
__global__ void transpose_half_kernel(const float* __restrict__ src, __half* __restrict__ dst,
                                      int R, int C, int dstride, int dbstride) {
    __shared__ float tile[32][33];
    int b  = blockIdx.z;
    int c0 = blockIdx.x * 32, r0 = blockIdx.y * 32;
    const float* s = src + (size_t)b * R * C;
    __half*      d = dst + (size_t)b * dbstride;
    int c = c0 + threadIdx.x;
    #pragma unroll
    for (int j = 0; j < 32; j += 8) {
        int r = r0 + threadIdx.y + j;
        tile[threadIdx.y + j][threadIdx.x] = s[(size_t)r * C + c];
    }
    __syncthreads();
    int rr = r0 + threadIdx.x;
    #pragma unroll
    for (int j = 0; j < 32; j += 8) {
        int cc = c0 + threadIdx.y + j;
        d[(size_t)cc * dstride + rr] = __float2half_rn(tile[threadIdx.x][threadIdx.y + j]);
    }
}

#define INS(E, SS)                                                                      \
    if ((E) < b2) {                                                                     \
        if ((E) < b0)      { b2 = b1; i2 = i1; b1 = b0; i1 = i0; b0 = (E); i0 = (SS); } \
        else if ((E) < b1) { b2 = b1; i2 = i1; b1 = (E); i1 = (SS); }                   \
        else               { b2 = (E); i2 = (SS); }                                     \
    }

// ---------------- quad-per-query top-3 (both stages) ----------------
// 4 lanes per query, 8 queries per warp, 64 queries per 256-thread block.
// Candidate reads are 8-way broadcast across query-groups; lane l covers
// candidates [4l, 4l+4) + 16k (unroll-4 scan, one gate per 4).
__global__ __launch_bounds__(256) void topk_quad_kernel(const float* __restrict__ xyzq,
                                                        const float* __restrict__ xyzs,
                                                        int N, int S,
                                                        int* __restrict__ idx,
                                                        float* __restrict__ w) {
    extern __shared__ float4 sh[];
    int b      = blockIdx.x / (N / 64);
    int n_base = (blockIdx.x % (N / 64)) * 64;
    int t    = threadIdx.x;
    int warp = t >> 5;
    int lane = t & 31;
    int g    = lane >> 2;
    int l    = lane & 3;
    int n    = n_base + warp * 8 + g;

    const float* sb = xyzs + (size_t)b * S * 3;
    for (int i = t; i < S; i += 256) {
        float x = sb[3 * i], y = sb[3 * i + 1], z = sb[3 * i + 2];
        sh[i] = make_float4(-2.f * x, -2.f * y, -2.f * z, x * x + y * y + z * z);
    }
    __syncthreads();

    const float* q = xyzq + ((size_t)b * N + n) * 3;
    float qx = q[0], qy = q[1], qz = q[2];

    float b0 = 1e30f, b1 = 1e30f, b2 = 1e30f;
    int   i0 = 0, i1 = 0, i2 = 0;

    #pragma unroll 2
    for (int s = 4 * l; s < S; s += 16) {
        float4 p0 = sh[s];
        float4 p1 = sh[s + 1];
        float4 p2 = sh[s + 2];
        float4 p3 = sh[s + 3];
        float e0 = fmaf(qx, p0.x, fmaf(qy, p0.y, fmaf(qz, p0.z, p0.w)));
        float e1 = fmaf(qx, p1.x, fmaf(qy, p1.y, fmaf(qz, p1.z, p1.w)));
        float e2 = fmaf(qx, p2.x, fmaf(qy, p2.y, fmaf(qz, p2.z, p2.w)));
        float e3 = fmaf(qx, p3.x, fmaf(qy, p3.y, fmaf(qz, p3.z, p3.w)));
        if (fminf(fminf(e0, e1), fminf(e2, e3)) < b2) {
            INS(e0, s);
            INS(e1, s + 1);
            INS(e2, s + 2);
            INS(e3, s + 3);
        }
    }

    // merge the 4 lane-lists within the quad (2 butterfly steps)
    #pragma unroll
    for (int off = 1; off <= 2; off <<= 1) {
        float c0 = __shfl_xor_sync(0xffffffffu, b0, off);
        float c1 = __shfl_xor_sync(0xffffffffu, b1, off);
        float c2 = __shfl_xor_sync(0xffffffffu, b2, off);
        int   j0 = __shfl_xor_sync(0xffffffffu, i0, off);
        int   j1 = __shfl_xor_sync(0xffffffffu, i1, off);
        int   j2 = __shfl_xor_sync(0xffffffffu, i2, off);
        INS(c0, j0);
        INS(c1, j1);
        INS(c2, j2);
    }

    if (l == 0) {
        float cn = qx * qx + qy * qy + qz * qz;
        float r0 = 1.f / (cn + b0 + 1e-8f);
        float r1 = 1.f / (cn + b1 + 1e-8f);
        float r2 = 1.f / (cn + b2 + 1e-8f);
        float inv = 1.f / (r0 + r1 + r2);
        size_t o = ((size_t)b * N + n) * 3;
        idx[o] = i0; idx[o + 1] = i1; idx[o + 2] = i2;
        w[o]   = r0 * inv; w[o + 1] = r1 * inv; w[o + 2] = r2 * inv;
    }
}
#undef INS

// ---------------- stage-1 gather: g_inter[:, 256:768] (fp16 in, fp16 out) ----------------
// grid (B*N1/32, D2C/64): 32-point x 64-channel tile per block, 256 threads.
__global__ __launch_bounds__(256) void gather1_kernel() {
    __shared__ int   sidx[32 * 3];
    __shared__ float sw[32 * 3];

    int b  = blockIdx.x / (N1 / 32);
    int n0 = (blockIdx.x % (N1 / 32)) * 32;
    int d0 = blockIdx.y * 64;
    int t  = threadIdx.x;

    if (t < 96) {
        size_t o = ((size_t)b * N1 + n0) * 3 + t;
        sidx[t] = g_idx1[o];
        sw[t]   = g_w1[o];
    }
    __syncthreads();

    const __half* xb = g_x2t + (size_t)b * N2 * D2C + d0;
    __half* dstb = g_inter + ((size_t)b * N1 + n0) * DI + D1C + d0;

    // 32 points x 8 chunks of 8 halves = 256 items, 1 per thread
    int p  = t >> 3;
    int c8 = (t & 7) * 8;
    int base = p * 3;
    float w0 = sw[base], w1 = sw[base + 1], w2 = sw[base + 2];
    const __half2* r0 = (const __half2*)(xb + (size_t)sidx[base]     * D2C + c8);
    const __half2* r1 = (const __half2*)(xb + (size_t)sidx[base + 1] * D2C + c8);
    const __half2* r2 = (const __half2*)(xb + (size_t)sidx[base + 2] * D2C + c8);
    __half2* dp = (__half2*)(dstb + (size_t)p * DI + c8);
    #pragma unroll
    for (int j = 0; j < 4; ++j) {
        float2 a = __half22float2(r0[j]);
        float2 c = __half22float2(r1[j]);
        float2 d = __half22float2(r2[j]);
        dp[j] = __floats2half2_rn(w0 * a.x + w1 * c.x + w2 * d.x,
                                  w0 * a.y + w1 * c.y + w2 * d.y);
    }
}

// ---------------- x0 copy: out[:, 0:128, :] (independent; overlapped branch) ----------
__global__ __launch_bounds__(256) void copy_x0_kernel(const float* __restrict__ x0,
                                                      float* __restrict__ out) {
    const int per_b = D0 * N0 / 4;          // float4s per batch
    int i = blockIdx.x * blockDim.x + threadIdx.x;
    if (i < B * per_b) {
        int b = i / per_b, r = i % per_b;
        reinterpret_cast<float4*>(out)[(size_t)b * (DT * N0 / 4) + r] =
            reinterpret_cast<const float4*>(x0)[i];
    }
}

// ---------------- stage-2 interp: out[:, 128:896] (fp16 gather) ----------------
// grid (B*N0/32, 12): one 32-point x 64-channel tile per block.
__global__ __launch_bounds__(256) void interp2_kernel(float* __restrict__ out) {
    __shared__ float acc[32 * 65];
    __shared__ int   sidx[32 * 3];
    __shared__ float sw[32 * 3];

    int b  = blockIdx.x / (N0 / 32);
    int n0 = (blockIdx.x % (N0 / 32)) * 32;
    int t  = threadIdx.x;
    int d0 = blockIdx.y * 64;

    if (t < 96) {
        size_t o = ((size_t)b * N0 + n0) * 3 + t;
        sidx[t] = g_idx2[o];
        sw[t]   = g_w2[o];
    }
    __syncthreads();

    const __half* interb = g_inter + (size_t)b * N1 * DI + d0;
    float* outb = out + (size_t)b * DT * N0 + (size_t)(D0 + d0) * N0 + n0;

    // gather-accumulate: 32 points x 8 chunks of 8 halves = 256 items (1/thread)
    {
        int p  = t >> 3;
        int c8 = (t & 7) * 8;
        int base = p * 3;
        float w0 = sw[base], w1 = sw[base + 1], w2 = sw[base + 2];
        const __half2* r0 = (const __half2*)(interb + (size_t)sidx[base]     * DI + c8);
        const __half2* r1 = (const __half2*)(interb + (size_t)sidx[base + 1] * DI + c8);
        const __half2* r2 = (const __half2*)(interb + (size_t)sidx[base + 2] * DI + c8);
        float* ap = acc + p * 65 + c8;
        #pragma unroll
        for (int j = 0; j < 4; ++j) {
            float2 a = __half22float2(r0[j]);
            float2 c = __half22float2(r1[j]);
            float2 d = __half22float2(r2[j]);
            ap[2 * j]     = w0 * a.x + w1 * c.x + w2 * d.x;
            ap[2 * j + 1] = w0 * a.y + w1 * c.y + w2 * d.y;
        }
    }
    __syncthreads();
    // write transposed: consecutive threads -> consecutive n (coalesced)
    #pragma unroll
    for (int e = t; e < 32 * 64; e += 256) {
        int dd = e >> 5;
        int p  = e & 31;
        outb[(size_t)dd * N0 + p] = acc[p * 65 + dd];
    }
}

// ---------------- stream/event singletons (host objects, created once, pre-capture) ----
struct GraphResources {
    cudaStream_t s2;
    cudaEvent_t  evF, evJ, evC;
    GraphResources() {
        cudaStreamCreateWithFlags(&s2, cudaStreamNonBlocking);
        cudaEventCreateWithFlags(&evF, cudaEventDisableTiming);
        cudaEventCreateWithFlags(&evJ, cudaEventDisableTiming);
        cudaEventCreateWithFlags(&evC, cudaEventDisableTiming);
    }
};
static GraphResources& gr() {
    static GraphResources r;
    return r;
}

// ---------------- launch ----------------
extern "C" void kernel_launch(void* const* d_in, const int* in_sizes, int n_in,
                              void* d_out, int out_size) {
    const float* xyz0 = (const float*)d_in[0];  // [4,8192,3]
    const float* xyz1 = (const float*)d_in[1];  // [4,2048,3]
    const float* xyz2 = (const float*)d_in[2];  // [4,512,3]
    const float* x0   = (const float*)d_in[3];  // [4,128,8192]
    const float* x1   = (const float*)d_in[4];  // [4,256,2048]
    const float* x2   = (const float*)d_in[5];  // [4,512,512]
    float* out = (float*)d_out;

    __half* x2t_ptr;   cudaGetSymbolAddress((void**)&x2t_ptr, g_x2t);
    __half* inter_ptr; cudaGetSymbolAddress((void**)&inter_ptr, g_inter);
    int* idx1_ptr;    cudaGetSymbolAddress((void**)&idx1_ptr, g_idx1);
    float* w1_ptr;    cudaGetSymbolAddress((void**)&w1_ptr, g_w1);
    int* idx2_ptr;    cudaGetSymbolAddress((void**)&idx2_ptr, g_idx2);
    float* w2_ptr;    cudaGetSymbolAddress((void**)&w2_ptr, g_w2);

    GraphResources& R = gr();

    // fork: side branch = stage-2 topk (xyz only) then the independent x0 copy
    cudaEventRecord(R.evF, 0);
    cudaStreamWaitEvent(R.s2, R.evF, 0);
    topk_quad_kernel<<<B * N0 / 64, 256, N1 * sizeof(float4), R.s2>>>(
        xyz0, xyz1, N0, N1, idx2_ptr, w2_ptr);
    cudaEventRecord(R.evJ, R.s2);                          // idx2/w2 ready
    copy_x0_kernel<<<(B * D0 * N0 / 4 + 255) / 256, 256, 0, R.s2>>>(x0, out);
    cudaEventRecord(R.evC, R.s2);                          // copy done (joined at end)

    // main branch: stage-1 chain
    {
        dim3 grid(N2 / 32, D2C / 32, B), blk(32, 8);
        transpose_half_kernel<<<grid, blk>>>(x2, x2t_ptr, D2C, N2, D2C, N2 * D2C);
    }
    // stage-1 top-3 (S=512): quad-per-query, 128 blocks x 256 thr, 8KB tile
    topk_quad_kernel<<<B * N1 / 64, 256, N2 * sizeof(float4)>>>(
        xyz1, xyz2, N1, N2, idx1_ptr, w1_ptr);
    {
        dim3 grid(B * (N1 / 32), D2C / 64);
        gather1_kernel<<<grid, 256>>>();
    }
    {
        dim3 grid(N1 / 32, D1C / 32, B), blk(32, 8);
        transpose_half_kernel<<<grid, blk>>>(x1, inter_ptr, D1C, N1, DI, N1 * DI);
    }

    // join idx2, run final interp (overlaps with the x0 copy on s2)
    cudaStreamWaitEvent(0, R.evJ, 0);
    {
        dim3 grid(B * (N0 / 32), 12);
        interp2_kernel<<<grid, 256>>>(out);
    }
    // join the copy branch before capture ends
    cudaStreamWaitEvent(0, R.evC, 0);
}

// round 17
// speedup vs baseline: 1.1965x; 1.1965x over previous
#include <cuda_runtime.h>
#include <cuda_fp16.h>
#include <math.h>

// ---------------- problem constants ----------------
#define B   4
#define N0  8192   // finest
#define N1  2048
#define N2  512    // coarsest
#define D0  128    // x0 channels
#define D1C 256    // x1 channels
#define D2C 512    // x2 channels
#define DI  768    // intermediate channels (D1C + D2C)
#define DT  896    // output channels (D0 + DI)

// ---------------- scratch (device globals; no allocation allowed) ----------------
__device__ __align__(16) __half g_x2t[B * N2 * D2C];   // x2 transposed, fp16 [B,S,D]
__device__ __align__(16) __half g_inter[B * N1 * DI];  // stage-1 result, fp16 point-major
__device__ int    g_idx1[B * N1 * 3];
__device__ float  g_w1[B * N1 * 3];
__device__ int    g_idx2[B * N0 * 3];
__device__ float  g_w2[B * N0 * 3];

// ---------------- transpose [B,R,C] fp32 -> fp16 dst (strided) ----------------
__global__ void transpose_half_kernel(const float* __restrict__ src, __half* __restrict__ dst,
                                      int R, int C, int dstride, int dbstride) {
    __shared__ float tile[32][33];
    int b  = blockIdx.z;
    int c0 = blockIdx.x * 32, r0 = blockIdx.y * 32;
    const float* s = src + (size_t)b * R * C;
    __half*      d = dst + (size_t)b * dbstride;
    int c = c0 + threadIdx.x;
    #pragma unroll
    for (int j = 0; j < 32; j += 8) {
        int r = r0 + threadIdx.y + j;
        tile[threadIdx.y + j][threadIdx.x] = s[(size_t)r * C + c];
    }
    __syncthreads();
    int rr = r0 + threadIdx.x;
    #pragma unroll
    for (int j = 0; j < 32; j += 8) {
        int cc = c0 + threadIdx.y + j;
        d[(size_t)cc * dstride + rr] = __float2half_rn(tile[threadIdx.x][threadIdx.y + j]);
    }
}

#define INS(E, SS)                                                                      \
    if ((E) < b2) {                                                                     \
        if ((E) < b0)      { b2 = b1; i2 = i1; b1 = b0; i1 = i0; b0 = (E); i0 = (SS); } \
        else if ((E) < b1) { b2 = b1; i2 = i1; b1 = (E); i1 = (SS); }                   \
        else               { b2 = (E); i2 = (SS); }                                     \
    }

// ---------------- octet-per-query top-3 (stage 1, S=512) ----------------
// 8 lanes per query, 4 queries per warp, 32 queries per 256-thread block.
// Candidate reads are 4-way broadcast across query-groups; 3 merge steps.
// Grid = B*N1/32 = 256 blocks (fills the chip, unlike quad at S=512).
__global__ __launch_bounds__(256) void topk_octet_kernel(const float* __restrict__ xyzq,
                                                         const float* __restrict__ xyzs,
                                                         int N, int S,
                                                         int* __restrict__ idx,
                                                         float* __restrict__ w) {
    extern __shared__ float4 sh[];
    int b      = blockIdx.x / (N / 32);
    int n_base = (blockIdx.x % (N / 32)) * 32;
    int t    = threadIdx.x;
    int warp = t >> 5;
    int lane = t & 31;
    int g    = lane >> 3;     // query group within warp (0..3)
    int l    = lane & 7;      // lane within octet
    int n    = n_base + warp * 4 + g;

    const float* sb = xyzs + (size_t)b * S * 3;
    for (int i = t; i < S; i += 256) {
        float x = sb[3 * i], y = sb[3 * i + 1], z = sb[3 * i + 2];
        sh[i] = make_float4(-2.f * x, -2.f * y, -2.f * z, x * x + y * y + z * z);
    }
    __syncthreads();

    const float* q = xyzq + ((size_t)b * N + n) * 3;
    float qx = q[0], qy = q[1], qz = q[2];

    float b0 = 1e30f, b1 = 1e30f, b2 = 1e30f;
    int   i0 = 0, i1 = 0, i2 = 0;

    // lane l scans candidates {2l, 2l+1, 2l+16, 2l+17, ...}
    #pragma unroll 4
    for (int s = 2 * l; s < S; s += 16) {
        float4 p0 = sh[s];
        float4 p1 = sh[s + 1];
        float e0 = fmaf(qx, p0.x, fmaf(qy, p0.y, fmaf(qz, p0.z, p0.w)));
        float e1 = fmaf(qx, p1.x, fmaf(qy, p1.y, fmaf(qz, p1.z, p1.w)));
        if (fminf(e0, e1) < b2) {
            INS(e0, s);
            INS(e1, s + 1);
        }
    }

    // merge the 8 lane-lists within the octet (3 butterfly steps)
    #pragma unroll
    for (int off = 1; off <= 4; off <<= 1) {
        float c0 = __shfl_xor_sync(0xffffffffu, b0, off);
        float c1 = __shfl_xor_sync(0xffffffffu, b1, off);
        float c2 = __shfl_xor_sync(0xffffffffu, b2, off);
        int   j0 = __shfl_xor_sync(0xffffffffu, i0, off);
        int   j1 = __shfl_xor_sync(0xffffffffu, i1, off);
        int   j2 = __shfl_xor_sync(0xffffffffu, i2, off);
        INS(c0, j0);
        INS(c1, j1);
        INS(c2, j2);
    }

    if (l == 0) {
        float cn = qx * qx + qy * qy + qz * qz;
        float r0 = 1.f / (cn + b0 + 1e-8f);
        float r1 = 1.f / (cn + b1 + 1e-8f);
        float r2 = 1.f / (cn + b2 + 1e-8f);
        float inv = 1.f / (r0 + r1 + r2);
        size_t o = ((size_t)b * N + n) * 3;
        idx[o] = i0; idx[o + 1] = i1; idx[o + 2] = i2;
        w[o]   = r0 * inv; w[o + 1] = r1 * inv; w[o + 2] = r2 * inv;
    }
}

// ---------------- quad-per-query top-3 (stage 2, S=2048) — R12 version ----------------
__global__ __launch_bounds__(256) void topk_quad_kernel(const float* __restrict__ xyzq,
                                                        const float* __restrict__ xyzs,
                                                        int N, int S,
                                                        int* __restrict__ idx,
                                                        float* __restrict__ w) {
    extern __shared__ float4 sh[];
    int b      = blockIdx.x / (N / 64);
    int n_base = (blockIdx.x % (N / 64)) * 64;
    int t    = threadIdx.x;
    int warp = t >> 5;
    int lane = t & 31;
    int g    = lane >> 2;
    int l    = lane & 3;
    int n    = n_base + warp * 8 + g;

    const float* sb = xyzs + (size_t)b * S * 3;
    for (int i = t; i < S; i += 256) {
        float x = sb[3 * i], y = sb[3 * i + 1], z = sb[3 * i + 2];
        sh[i] = make_float4(-2.f * x, -2.f * y, -2.f * z, x * x + y * y + z * z);
    }
    __syncthreads();

    const float* q = xyzq + ((size_t)b * N + n) * 3;
    float qx = q[0], qy = q[1], qz = q[2];

    float b0 = 1e30f, b1 = 1e30f, b2 = 1e30f;
    int   i0 = 0, i1 = 0, i2 = 0;

    #pragma unroll 4
    for (int s = 2 * l; s < S; s += 8) {
        float4 p0 = sh[s];
        float4 p1 = sh[s + 1];
        float e0 = fmaf(qx, p0.x, fmaf(qy, p0.y, fmaf(qz, p0.z, p0.w)));
        float e1 = fmaf(qx, p1.x, fmaf(qy, p1.y, fmaf(qz, p1.z, p1.w)));
        if (fminf(e0, e1) < b2) {
            INS(e0, s);
            INS(e1, s + 1);
        }
    }

    #pragma unroll
    for (int off = 1; off <= 2; off <<= 1) {
        float c0 = __shfl_xor_sync(0xffffffffu, b0, off);
        float c1 = __shfl_xor_sync(0xffffffffu, b1, off);
        float c2 = __shfl_xor_sync(0xffffffffu, b2, off);
        int   j0 = __shfl_xor_sync(0xffffffffu, i0, off);
        int   j1 = __shfl_xor_sync(0xffffffffu, i1, off);
        int   j2 = __shfl_xor_sync(0xffffffffu, i2, off);
        INS(c0, j0);
        INS(c1, j1);
        INS(c2, j2);
    }

    if (l == 0) {
        float cn = qx * qx + qy * qy + qz * qz;
        float r0 = 1.f / (cn + b0 + 1e-8f);
        float r1 = 1.f / (cn + b1 + 1e-8f);
        float r2 = 1.f / (cn + b2 + 1e-8f);
        float inv = 1.f / (r0 + r1 + r2);
        size_t o = ((size_t)b * N + n) * 3;
        idx[o] = i0; idx[o + 1] = i1; idx[o + 2] = i2;
        w[o]   = r0 * inv; w[o + 1] = r1 * inv; w[o + 2] = r2 * inv;
    }
}
#undef INS

// ---------------- stage-1 gather: g_inter[:, 256:768] (fp16 in, fp16 out) ----------------
// grid (B*N1/32, D2C/64): 32-point x 64-channel tile per block, 256 threads.
__global__ __launch_bounds__(256) void gather1_kernel() {
    __shared__ int   sidx[32 * 3];
    __shared__ float sw[32 * 3];

    int b  = blockIdx.x / (N1 / 32);
    int n0 = (blockIdx.x % (N1 / 32)) * 32;
    int d0 = blockIdx.y * 64;
    int t  = threadIdx.x;

    if (t < 96) {
        size_t o = ((size_t)b * N1 + n0) * 3 + t;
        sidx[t] = g_idx1[o];
        sw[t]   = g_w1[o];
    }
    __syncthreads();

    const __half* xb = g_x2t + (size_t)b * N2 * D2C + d0;
    __half* dstb = g_inter + ((size_t)b * N1 + n0) * DI + D1C + d0;

    int p  = t >> 3;
    int c8 = (t & 7) * 8;
    int base = p * 3;
    float w0 = sw[base], w1 = sw[base + 1], w2 = sw[base + 2];
    const __half2* r0 = (const __half2*)(xb + (size_t)sidx[base]     * D2C + c8);
    const __half2* r1 = (const __half2*)(xb + (size_t)sidx[base + 1] * D2C + c8);
    const __half2* r2 = (const __half2*)(xb + (size_t)sidx[base + 2] * D2C + c8);
    __half2* dp = (__half2*)(dstb + (size_t)p * DI + c8);
    #pragma unroll
    for (int j = 0; j < 4; ++j) {
        float2 a = __half22float2(r0[j]);
        float2 c = __half22float2(r1[j]);
        float2 d = __half22float2(r2[j]);
        dp[j] = __floats2half2_rn(w0 * a.x + w1 * c.x + w2 * d.x,
                                  w0 * a.y + w1 * c.y + w2 * d.y);
    }
}

// ---------------- x0 copy: out[:, 0:128, :] (independent; overlapped branch) ----------
__global__ __launch_bounds__(256) void copy_x0_kernel(const float* __restrict__ x0,
                                                      float* __restrict__ out) {
    const int per_b = D0 * N0 / 4;          // float4s per batch
    int i = blockIdx.x * blockDim.x + threadIdx.x;
    if (i < B * per_b) {
        int b = i / per_b, r = i % per_b;
        reinterpret_cast<float4*>(out)[(size_t)b * (DT * N0 / 4) + r] =
            reinterpret_cast<const float4*>(x0)[i];
    }
}

// ---------------- stage-2 interp: out[:, 128:896] (fp16 gather) ----------------
// grid (B*N0/32, 12): one 32-point x 64-channel tile per block.
__global__ __launch_bounds__(256) void interp2_kernel(float* __restrict__ out) {
    __shared__ float acc[32 * 65];
    __shared__ int   sidx[32 * 3];
    __shared__ float sw[32 * 3];

    int b  = blockIdx.x / (N0 / 32);
    int n0 = (blockIdx.x % (N0 / 32)) * 32;
    int t  = threadIdx.x;
    int d0 = blockIdx.y * 64;

    if (t < 96) {
        size_t o = ((size_t)b * N0 + n0) * 3 + t;
        sidx[t] = g_idx2[o];
        sw[t]   = g_w2[o];
    }
    __syncthreads();

    const __half* interb = g_inter + (size_t)b * N1 * DI + d0;
    float* outb = out + (size_t)b * DT * N0 + (size_t)(D0 + d0) * N0 + n0;

    {
        int p  = t >> 3;
        int c8 = (t & 7) * 8;
        int base = p * 3;
        float w0 = sw[base], w1 = sw[base + 1], w2 = sw[base + 2];
        const __half2* r0 = (const __half2*)(interb + (size_t)sidx[base]     * DI + c8);
        const __half2* r1 = (const __half2*)(interb + (size_t)sidx[base + 1] * DI + c8);
        const __half2* r2 = (const __half2*)(interb + (size_t)sidx[base + 2] * DI + c8);
        float* ap = acc + p * 65 + c8;
        #pragma unroll
        for (int j = 0; j < 4; ++j) {
            float2 a = __half22float2(r0[j]);
            float2 c = __half22float2(r1[j]);
            float2 d = __half22float2(r2[j]);
            ap[2 * j]     = w0 * a.x + w1 * c.x + w2 * d.x;
            ap[2 * j + 1] = w0 * a.y + w1 * c.y + w2 * d.y;
        }
    }
    __syncthreads();
    #pragma unroll
    for (int e = t; e < 32 * 64; e += 256) {
        int dd = e >> 5;
        int p  = e & 31;
        outb[(size_t)dd * N0 + p] = acc[p * 65 + dd];
    }
}

// ---------------- stream/event singletons (host objects, created once, pre-capture) ----
struct GraphResources {
    cudaStream_t s2;
    cudaEvent_t  evF, evJ, evC;
    GraphResources() {
        cudaStreamCreateWithFlags(&s2, cudaStreamNonBlocking);
        cudaEventCreateWithFlags(&evF, cudaEventDisableTiming);
        cudaEventCreateWithFlags(&evJ, cudaEventDisableTiming);
        cudaEventCreateWithFlags(&evC, cudaEventDisableTiming);
    }
};
static GraphResources& gr() {
    static GraphResources r;
    return r;
}

// ---------------- launch ----------------
extern "C" void kernel_launch(void* const* d_in, const int* in_sizes, int n_in,
                              void* d_out, int out_size) {
    const float* xyz0 = (const float*)d_in[0];  // [4,8192,3]
    const float* xyz1 = (const float*)d_in[1];  // [4,2048,3]
    const float* xyz2 = (const float*)d_in[2];  // [4,512,3]
    const float* x0   = (const float*)d_in[3];  // [4,128,8192]
    const float* x1   = (const float*)d_in[4];  // [4,256,2048]
    const float* x2   = (const float*)d_in[5];  // [4,512,512]
    float* out = (float*)d_out;

    __half* x2t_ptr;   cudaGetSymbolAddress((void**)&x2t_ptr, g_x2t);
    __half* inter_ptr; cudaGetSymbolAddress((void**)&inter_ptr, g_inter);
    int* idx1_ptr;    cudaGetSymbolAddress((void**)&idx1_ptr, g_idx1);
    float* w1_ptr;    cudaGetSymbolAddress((void**)&w1_ptr, g_w1);
    int* idx2_ptr;    cudaGetSymbolAddress((void**)&idx2_ptr, g_idx2);
    float* w2_ptr;    cudaGetSymbolAddress((void**)&w2_ptr, g_w2);

    GraphResources& R = gr();

    // fork: side branch = stage-2 topk (xyz only) then the independent x0 copy
    cudaEventRecord(R.evF, 0);
    cudaStreamWaitEvent(R.s2, R.evF, 0);
    topk_quad_kernel<<<B * N0 / 64, 256, N1 * sizeof(float4), R.s2>>>(
        xyz0, xyz1, N0, N1, idx2_ptr, w2_ptr);
    cudaEventRecord(R.evJ, R.s2);                          // idx2/w2 ready
    copy_x0_kernel<<<(B * D0 * N0 / 4 + 255) / 256, 256, 0, R.s2>>>(x0, out);
    cudaEventRecord(R.evC, R.s2);                          // copy done (joined at end)

    // main branch: stage-1 chain
    {
        dim3 grid(N2 / 32, D2C / 32, B), blk(32, 8);
        transpose_half_kernel<<<grid, blk>>>(x2, x2t_ptr, D2C, N2, D2C, N2 * D2C);
    }
    // stage-1 top-3 (S=512): octet-per-query, 256 blocks x 256 thr, 8KB tile
    topk_octet_kernel<<<B * N1 / 32, 256, N2 * sizeof(float4)>>>(
        xyz1, xyz2, N1, N2, idx1_ptr, w1_ptr);
    {
        dim3 grid(B * (N1 / 32), D2C / 64);
        gather1_kernel<<<grid, 256>>>();
    }
    {
        dim3 grid(N1 / 32, D1C / 32, B), blk(32, 8);
        transpose_half_kernel<<<grid, blk>>>(x1, inter_ptr, D1C, N1, DI, N1 * DI);
    }

    // join idx2, run final interp (overlaps with the x0 copy on s2)
    cudaStreamWaitEvent(0, R.evJ, 0);
    {
        dim3 grid(B * (N0 / 32), 12);
        interp2_kernel<<<grid, 256>>>(out);
    }
    // join the copy branch before capture ends
    cudaStreamWaitEvent(0, R.evC, 0);
}